// round 11
// baseline (speedup 1.0000x reference)
#include <cuda_runtime.h>
#include <cstdint>

#define TWO_PI_F 6.28318530717958647692f

namespace {

constexpr int B = 4, S = 4096, V = 64, D = 128;

struct __align__(16) WSmem {
    float xs[2][V][2];   // [pair][j][half] char embeddings
    float hs[2][V][2];   // layer-0 out
    float ls[2][D][2];   // layernorm out (reused layer1/layer2)
    float h1[2][D][2];   // layer-1 out / rv spill / t2 spill
};

typedef unsigned long long ull;

__device__ __forceinline__ ull dup2(float a) {
    ull r; unsigned int u = __float_as_uint(a);
    asm("mov.b64 %0, {%1, %1};" : "=l"(r) : "r"(u));
    return r;
}
__device__ __forceinline__ ull pk2(float a, float b) {
    ull r;
    asm("mov.b64 %0, {%1, %2};" : "=l"(r) : "r"(__float_as_uint(a)), "r"(__float_as_uint(b)));
    return r;
}
__device__ __forceinline__ float2 unpk(ull v) {
    unsigned int lo, hi;
    asm("mov.b64 {%0, %1}, %2;" : "=r"(lo), "=r"(hi) : "l"(v));
    return make_float2(__uint_as_float(lo), __uint_as_float(hi));
}
__device__ __forceinline__ void ffma2(ull& d, ull a, ull b) {
    asm("fma.rn.f32x2 %0, %1, %2, %0;" : "+l"(d) : "l"(a), "l"(b));
}
__device__ __forceinline__ ull addp(ull a, ull b) {
    ull r;
    asm("add.rn.f32x2 %0, %1, %2;" : "=l"(r) : "l"(a), "l"(b));
    return r;
}

// cos(2*pi*s/p) with exact integer range reduction (q off-by-one shifts by a
// full period, invisible to cos).
__device__ __forceinline__ float phase_slow(float sf, float pf, float rcp) {
    float q = floorf(sf * rcp);
    float r = fmaf(-q, pf, sf);
    return __cosf(TWO_PI_F * (r * rcp));
}

__device__ __forceinline__ ull ld_ull2_lo(const float* p, ull& hi) {
    ulonglong2 v = *reinterpret_cast<const ulonglong2*>(p);
    hi = v.y; return v.x;
}

} // namespace

// ---- row-paired weight tables (position-invariant, rebuilt each launch) ----
// pq*: [j][i2] float4 = (w[i2][j], rcp(i2,j), w[i2+half][j], rcp(i2+half,j))
__device__ float4 g_pq0[V * 32];     // charP, half=32
__device__ float4 g_mr4[V * 64];     // (M1_i, R1_i, M1_{i+64}, R1_{i+64})
__device__ float4 g_pq1[D * 64];     // P1, half=64
__device__ float4 g_pq2[D * 64];     // P2, half=64
__device__ float2 g_m2p[D * 64];     // (M2_i, M2_{i+64})

extern "C" __global__ void __launch_bounds__(256)
prep_weights(const float* __restrict__ charP, const float* __restrict__ M1,
             const float* __restrict__ R1,    const float* __restrict__ P1,
             const float* __restrict__ P2,    const float* __restrict__ M2)
{
    int t = blockIdx.x * blockDim.x + threadIdx.x;
    if (t < 2048) {                                   // g_pq0: 64 j x 32 i2
        int j = t >> 5, i2 = t & 31;
        g_pq0[t] = make_float4(
            charP[i2 * V + j],        1.0f / (float)(i2 * V + j + 2),
            charP[(i2 + 32) * V + j], 1.0f / (float)((i2 + 32) * V + j + 2));
    } else if (t < 6144) {                            // g_mr4: 64 j x 64 i2
        int u = t - 2048; int j = u >> 6, i2 = u & 63;
        g_mr4[u] = make_float4(M1[i2 * V + j], R1[i2 * V + j],
                               M1[(i2 + 64) * V + j], R1[(i2 + 64) * V + j]);
    } else if (t < 14336) {                           // g_pq1: 128 j x 64 i2
        int u = t - 6144; int j = u >> 6, i2 = u & 63;
        g_pq1[u] = make_float4(
            P1[i2 * D + j],        1.0f / (float)(i2 * D + j + 2),
            P1[(i2 + 64) * D + j], 1.0f / (float)((i2 + 64) * D + j + 2));
    } else if (t < 22528) {                           // g_pq2
        int u = t - 14336; int j = u >> 6, i2 = u & 63;
        g_pq2[u] = make_float4(
            P2[i2 * D + j],        1.0f / (float)(i2 * D + j + 2),
            P2[(i2 + 64) * D + j], 1.0f / (float)((i2 + 64) * D + j + 2));
    } else if (t < 30720) {                           // g_m2p
        int u = t - 22528; int j = u >> 6, i2 = u & 63;
        g_m2p[u] = make_float2(M2[i2 * D + j], M2[(i2 + 64) * D + j]);
    }
}

namespace {

// pos_nk over D for 4 rows (t, t+32, t+64, t+96). Row order in acc:
// r0=t, r1=t+32, r2=t+64, r3=t+96. Packs: tbl[j*64+t] covers r0/r2,
// tbl[j*64+t+32] covers r1/r3.
__device__ __forceinline__ void posnk4(
    const float4* __restrict__ tbl, const float* __restrict__ lsbase,
    float sf, int t, ull (&acc)[4][2])
{
    const float pb0 = (float)((t      ) * D + 2);
    const float pb1 = (float)((t + 32 ) * D + 2);
    const float pb2 = (float)((t + 64 ) * D + 2);
    const float pb3 = (float)((t + 96 ) * D + 2);
    #pragma unroll 2
    for (int j2 = 0; j2 < D / 2; ++j2) {
        ull x0y, x1y;
        ull x0x = ld_ull2_lo(lsbase + (2 * j2) * 2, x0y);
        ull x1x = ld_ull2_lo(lsbase + (D + 2 * j2) * 2, x1y);
        #pragma unroll
        for (int e = 0; e < 2; ++e) {
            int j = 2 * j2 + e;
            float jf = (float)j;
            float4 wa = tbl[j * 64 + t];
            float4 wb = tbl[j * 64 + t + 32];
            float a0 = wa.x * phase_slow(sf, pb0 + jf, wa.y);
            float a1 = wb.x * phase_slow(sf, pb1 + jf, wb.y);
            float a2 = wa.z * phase_slow(sf, pb2 + jf, wa.w);
            float a3 = wb.z * phase_slow(sf, pb3 + jf, wb.w);
            ull xm0 = e ? x0y : x0x;
            ull xm1 = e ? x1y : x1x;
            ffma2(acc[0][0], dup2(a0), xm0); ffma2(acc[0][1], dup2(a0), xm1);
            ffma2(acc[1][0], dup2(a1), xm0); ffma2(acc[1][1], dup2(a1), xm1);
            ffma2(acc[2][0], dup2(a2), xm0); ffma2(acc[2][1], dup2(a2), xm1);
            ffma2(acc[3][0], dup2(a3), xm0); ffma2(acc[3][1], dup2(a3), xm1);
        }
    }
}

} // namespace

extern "C" __global__ void __launch_bounds__(128, 8)
hier_kernel(const int* __restrict__ tokens, const int* __restrict__ positions,
            const float* __restrict__ emb,
            const float* __restrict__ g1, const float* __restrict__ b1v,
            const float* __restrict__ g2, const float* __restrict__ b2v,
            float* __restrict__ out)
{
    __shared__ WSmem sm[4];

    const int tid  = (int)threadIdx.x;
    const int wid  = tid >> 5;            // warp = position
    const int t    = tid & 31;            // lane
    const int sidx = blockIdx.x * 4 + wid;
    const float sf = (float)positions[sidx];
    WSmem& W = sm[wid];

    // ---- gather char embeddings ------------------------------------------
    {
        #pragma unroll
        for (int b = 0; b < B; ++b) {
            int tk = tokens[b * S + sidx];
            #pragma unroll
            for (int k = 0; k < 2; ++k) {
                int j = t + 32 * k;
                W.xs[b >> 1][j][b & 1] = emb[tk * V + j];
            }
        }
    }
    __syncwarp();

    // ---- layer 0: rows t, t+32 over V ------------------------------------
    {
        const float pbA = (float)(t * V + 2);
        const float pbB = (float)((t + 32) * V + 2);
        ull hA0 = 0, hA1 = 0, hB0 = 0, hB1 = 0;
        #pragma unroll 4
        for (int j2 = 0; j2 < V / 2; ++j2) {
            ull x0y, x1y;
            ull x0x = ld_ull2_lo(&W.xs[0][2 * j2][0], x0y);
            ull x1x = ld_ull2_lo(&W.xs[1][2 * j2][0], x1y);
            #pragma unroll
            for (int e = 0; e < 2; ++e) {
                int j = 2 * j2 + e;
                float jf = (float)j;
                float4 w = g_pq0[j * 32 + t];
                float aA = w.x * phase_slow(sf, pbA + jf, w.y);
                float aB = w.z * phase_slow(sf, pbB + jf, w.w);
                ull adA = dup2(aA), adB = dup2(aB);
                ull xm0 = e ? x0y : x0x;
                ull xm1 = e ? x1y : x1x;
                ffma2(hA0, adA, xm0); ffma2(hA1, adA, xm1);
                ffma2(hB0, adB, xm0); ffma2(hB1, adB, xm1);
            }
        }
        *reinterpret_cast<ull*>(&W.hs[0][t][0])      = hA0;
        *reinterpret_cast<ull*>(&W.hs[1][t][0])      = hA1;
        *reinterpret_cast<ull*>(&W.hs[0][t + 32][0]) = hB0;
        *reinterpret_cast<ull*>(&W.hs[1][t + 32][0]) = hB1;
    }
    __syncwarp();

    // warp-level layernorm over 128 rows, 4 rows/thread.
    auto layernorm4 = [&](float (&tv)[4][B], const float* gg, const float* bb,
                          float (&nv)[4][B]) {
        float s1[B], s2[B];
        #pragma unroll
        for (int b = 0; b < B; ++b) {
            s1[b] = tv[0][b] + tv[1][b] + tv[2][b] + tv[3][b];
            s2[b] = tv[0][b] * tv[0][b] + tv[1][b] * tv[1][b]
                  + tv[2][b] * tv[2][b] + tv[3][b] * tv[3][b];
        }
        #pragma unroll
        for (int o = 16; o; o >>= 1) {
            #pragma unroll
            for (int b = 0; b < B; ++b) {
                s1[b] += __shfl_xor_sync(0xffffffffu, s1[b], o);
                s2[b] += __shfl_xor_sync(0xffffffffu, s2[b], o);
            }
        }
        float gv[4], bv[4];
        #pragma unroll
        for (int r = 0; r < 4; ++r) { gv[r] = gg[t + 32 * r]; bv[r] = bb[t + 32 * r]; }
        #pragma unroll
        for (int b = 0; b < B; ++b) {
            float mu  = s1[b] * (1.0f / D);
            float var = fmaf(s2[b], 1.0f / D, -mu * mu);
            float rs  = rsqrtf(var + 1e-5f);
            #pragma unroll
            for (int r = 0; r < 4; ++r)
                nv[r][b] = fmaf((tv[r][b] - mu) * rs, gv[r], bv[r]);
        }
    };

    // ---- layer 1 R-pass: rv = R1 @ h, spill to h1 smem -------------------
    {
        ull rv[4][2] = {{0,0},{0,0},{0,0},{0,0}};
        #pragma unroll 4
        for (int j2 = 0; j2 < V / 2; ++j2) {
            ull x0y, x1y;
            ull x0x = ld_ull2_lo(&W.hs[0][2 * j2][0], x0y);
            ull x1x = ld_ull2_lo(&W.hs[1][2 * j2][0], x1y);
            #pragma unroll
            for (int e = 0; e < 2; ++e) {
                int j = 2 * j2 + e;
                float4 wa = g_mr4[j * 64 + t];
                float4 wb = g_mr4[j * 64 + t + 32];
                ull xm0 = e ? x0y : x0x;
                ull xm1 = e ? x1y : x1x;
                ffma2(rv[0][0], dup2(wa.y), xm0); ffma2(rv[0][1], dup2(wa.y), xm1);
                ffma2(rv[1][0], dup2(wb.y), xm0); ffma2(rv[1][1], dup2(wb.y), xm1);
                ffma2(rv[2][0], dup2(wa.w), xm0); ffma2(rv[2][1], dup2(wa.w), xm1);
                ffma2(rv[3][0], dup2(wb.w), xm0); ffma2(rv[3][1], dup2(wb.w), xm1);
            }
        }
        #pragma unroll
        for (int r = 0; r < 4; ++r) {       // same-lane spill, no sync needed
            *reinterpret_cast<ull*>(&W.h1[0][t + 32 * r][0]) = rv[r][0];
            *reinterpret_cast<ull*>(&W.h1[1][t + 32 * r][0]) = rv[r][1];
        }
    }

    // ---- layer 1 M-pass: t1 = M1 @ h, layernorm -> ls --------------------
    {
        ull t1p[4][2] = {{0,0},{0,0},{0,0},{0,0}};
        #pragma unroll 4
        for (int j2 = 0; j2 < V / 2; ++j2) {
            ull x0y, x1y;
            ull x0x = ld_ull2_lo(&W.hs[0][2 * j2][0], x0y);
            ull x1x = ld_ull2_lo(&W.hs[1][2 * j2][0], x1y);
            #pragma unroll
            for (int e = 0; e < 2; ++e) {
                int j = 2 * j2 + e;
                float4 wa = g_mr4[j * 64 + t];
                float4 wb = g_mr4[j * 64 + t + 32];
                ull xm0 = e ? x0y : x0x;
                ull xm1 = e ? x1y : x1x;
                ffma2(t1p[0][0], dup2(wa.x), xm0); ffma2(t1p[0][1], dup2(wa.x), xm1);
                ffma2(t1p[1][0], dup2(wb.x), xm0); ffma2(t1p[1][1], dup2(wb.x), xm1);
                ffma2(t1p[2][0], dup2(wa.z), xm0); ffma2(t1p[2][1], dup2(wa.z), xm1);
                ffma2(t1p[3][0], dup2(wb.z), xm0); ffma2(t1p[3][1], dup2(wb.z), xm1);
            }
        }
        float tv[4][B], nv[4][B];
        #pragma unroll
        for (int r = 0; r < 4; ++r) {
            float2 a0 = unpk(t1p[r][0]), a1 = unpk(t1p[r][1]);
            tv[r][0] = a0.x; tv[r][1] = a0.y; tv[r][2] = a1.x; tv[r][3] = a1.y;
        }
        layernorm4(tv, g1, b1v, nv);
        #pragma unroll
        for (int r = 0; r < 4; ++r) {
            *reinterpret_cast<ull*>(&W.ls[0][t + 32 * r][0]) = pk2(nv[r][0], nv[r][1]);
            *reinterpret_cast<ull*>(&W.ls[1][t + 32 * r][0]) = pk2(nv[r][2], nv[r][3]);
        }
    }
    __syncwarp();

    // ---- layer 1 pos_nk + residual ---------------------------------------
    {
        ull n1[4][2] = {{0,0},{0,0},{0,0},{0,0}};
        posnk4(g_pq1, &W.ls[0][0][0], sf, t, n1);
        #pragma unroll
        for (int r = 0; r < 4; ++r) {       // same-lane rv readback + overwrite
            ull rv0 = *reinterpret_cast<ull*>(&W.h1[0][t + 32 * r][0]);
            ull rv1 = *reinterpret_cast<ull*>(&W.h1[1][t + 32 * r][0]);
            *reinterpret_cast<ull*>(&W.h1[0][t + 32 * r][0]) = addp(n1[r][0], rv0);
            *reinterpret_cast<ull*>(&W.h1[1][t + 32 * r][0]) = addp(n1[r][1], rv1);
        }
    }
    __syncwarp();

    // ---- layer 2: t2 = M2 @ h1, layernorm -> ls, spill t2 -> h1 ----------
    {
        ull t2p[4][2] = {{0,0},{0,0},{0,0},{0,0}};
        #pragma unroll 2
        for (int j2 = 0; j2 < D / 2; ++j2) {
            ull x0y, x1y;
            ull x0x = ld_ull2_lo(&W.h1[0][2 * j2][0], x0y);
            ull x1x = ld_ull2_lo(&W.h1[1][2 * j2][0], x1y);
            #pragma unroll
            for (int e = 0; e < 2; ++e) {
                int j = 2 * j2 + e;
                float2 ma = g_m2p[j * 64 + t];
                float2 mb = g_m2p[j * 64 + t + 32];
                ull xm0 = e ? x0y : x0x;
                ull xm1 = e ? x1y : x1x;
                ffma2(t2p[0][0], dup2(ma.x), xm0); ffma2(t2p[0][1], dup2(ma.x), xm1);
                ffma2(t2p[1][0], dup2(mb.x), xm0); ffma2(t2p[1][1], dup2(mb.x), xm1);
                ffma2(t2p[2][0], dup2(ma.y), xm0); ffma2(t2p[2][1], dup2(ma.y), xm1);
                ffma2(t2p[3][0], dup2(mb.y), xm0); ffma2(t2p[3][1], dup2(mb.y), xm1);
            }
        }
        float tv[4][B], nv[4][B];
        #pragma unroll
        for (int r = 0; r < 4; ++r) {
            float2 a0 = unpk(t2p[r][0]), a1 = unpk(t2p[r][1]);
            tv[r][0] = a0.x; tv[r][1] = a0.y; tv[r][2] = a1.x; tv[r][3] = a1.y;
        }
        layernorm4(tv, g2, b2v, nv);
        __syncwarp();                        // all lanes done reading h1
        #pragma unroll
        for (int r = 0; r < 4; ++r) {
            *reinterpret_cast<ull*>(&W.ls[0][t + 32 * r][0]) = pk2(nv[r][0], nv[r][1]);
            *reinterpret_cast<ull*>(&W.ls[1][t + 32 * r][0]) = pk2(nv[r][2], nv[r][3]);
            *reinterpret_cast<ull*>(&W.h1[0][t + 32 * r][0]) = t2p[r][0];  // t2 spill
            *reinterpret_cast<ull*>(&W.h1[1][t + 32 * r][0]) = t2p[r][1];
        }
    }
    __syncwarp();

    // ---- layer 2 pos_nk + shared residual t2 -----------------------------
    {
        ull ov[4][2] = {{0,0},{0,0},{0,0},{0,0}};
        posnk4(g_pq2, &W.ls[0][0][0], sf, t, ov);
        #pragma unroll
        for (int r = 0; r < 4; ++r) {
            int i = t + 32 * r;
            ull t20 = *reinterpret_cast<ull*>(&W.h1[0][i][0]);
            ull t21 = *reinterpret_cast<ull*>(&W.h1[1][i][0]);
            float2 o0 = unpk(addp(ov[r][0], t20));
            float2 o1 = unpk(addp(ov[r][1], t21));
            out[(0 * S + sidx) * D + i] = o0.x;
            out[(1 * S + sidx) * D + i] = o0.y;
            out[(2 * S + sidx) * D + i] = o1.x;
            out[(3 * S + sidx) * D + i] = o1.y;
        }
    }
}

extern "C" void kernel_launch(void* const* d_in, const int* in_sizes, int n_in,
                              void* d_out, int out_size) {
    const int*   tokens    = (const int*)d_in[0];
    const int*   positions = (const int*)d_in[1];
    const float* emb       = (const float*)d_in[2];
    const float* charP     = (const float*)d_in[3];
    const float* M1        = (const float*)d_in[4];
    const float* P1        = (const float*)d_in[5];
    const float* g1        = (const float*)d_in[6];
    const float* b1        = (const float*)d_in[7];
    const float* R1        = (const float*)d_in[8];
    const float* M2        = (const float*)d_in[9];
    const float* P2        = (const float*)d_in[10];
    const float* g2        = (const float*)d_in[11];
    const float* b2        = (const float*)d_in[12];
    float* out = (float*)d_out;

    prep_weights<<<(30720 + 255) / 256, 256>>>(charP, M1, R1, P1, P2, M2);

    hier_kernel<<<S / 4, 128>>>(tokens, positions, emb, g1, b1, g2, b2, out);
}